// round 2
// baseline (speedup 1.0000x reference)
#include <cuda_runtime.h>

// Problem shape
#define B_DIM 4096
#define T_DIM 256
#define D_DIM 64
#define TD (T_DIM * D_DIM)   // stride per batch row in inputs/out

#define PA 65                // padded row stride for expm smem buffers
#define PBX 132              // xt row stride (float4-aligned)

typedef unsigned long long u64;

// Precomputed expm(K*t), stored TRANSPOSED: g_matsT[t*4096 + j*64 + i] = mats[t][i][j]
__device__ float g_matsT[T_DIM * D_DIM * D_DIM];

// ---------------- packed f32x2 helpers ----------------
__device__ __forceinline__ u64 ffma2(u64 a, u64 b, u64 c) {
    u64 d;
    asm("fma.rn.f32x2 %0, %1, %2, %3;" : "=l"(d) : "l"(a), "l"(b), "l"(c));
    return d;
}
__device__ __forceinline__ u64 pack2(float x) {
    u64 d;
    unsigned int u = __float_as_uint(x);
    asm("mov.b64 %0, {%1, %1};" : "=l"(d) : "r"(u));
    return d;
}
__device__ __forceinline__ float2 unpack2(u64 v) {
    unsigned int lo, hi;
    asm("mov.b64 {%0, %1}, %2;" : "=r"(lo), "=r"(hi) : "l"(v));
    return make_float2(__uint_as_float(lo), __uint_as_float(hi));
}

// ---------------- expm phase (unchanged from R1) ----------------
__device__ __forceinline__ void mm64(float* __restrict__ C,
                                     const float* __restrict__ A,
                                     const float* __restrict__ B,
                                     int ty, int tx) {
    float acc[4][4];
#pragma unroll
    for (int r = 0; r < 4; r++)
#pragma unroll
        for (int c = 0; c < 4; c++) acc[r][c] = 0.f;

#pragma unroll 4
    for (int k = 0; k < 64; k++) {
        float a[4], b[4];
#pragma unroll
        for (int r = 0; r < 4; r++) a[r] = A[(ty * 4 + r) * PA + k];
#pragma unroll
        for (int c = 0; c < 4; c++) b[c] = B[k * PA + tx * 4 + c];
#pragma unroll
        for (int r = 0; r < 4; r++)
#pragma unroll
            for (int c = 0; c < 4; c++) acc[r][c] = fmaf(a[r], b[c], acc[r][c]);
    }
#pragma unroll
    for (int r = 0; r < 4; r++)
#pragma unroll
        for (int c = 0; c < 4; c++) C[(ty * 4 + r) * PA + tx * 4 + c] = acc[r][c];
}

extern "C" __global__ void __launch_bounds__(256)
expm_kernel(const float* __restrict__ Kmat, const float* __restrict__ time) {
    extern __shared__ float sm[];
    float* a = sm;
    float* b = a + 64 * PA;
    float* c = b + 64 * PA;
    float* d = c + 64 * PA;
    float* e = d + 64 * PA;
    float* f = e + 64 * PA;

    const int tid = threadIdx.x;
    const int ty = tid >> 4, tx = tid & 15;
    const int bt = blockIdx.x;
    const float t = time[bt] * 0.5f;

#pragma unroll
    for (int l = 0; l < 16; l++) {
        int idx = tid + l * 256;
        a[(idx >> 6) * PA + (idx & 63)] = Kmat[idx] * t;
    }
    __syncthreads();

    mm64(b, a, a, ty, tx);
    __syncthreads();
    mm64(c, b, b, ty, tx);
    mm64(d, b, a, ty, tx);
    __syncthreads();

#pragma unroll
    for (int l = 0; l < 16; l++) {
        int idx = tid + l * 256;
        int i = idx >> 6, j = idx & 63;
        int off = i * PA + j;
        float v = 2.4801587301e-5f * ((i == j) ? 1.f : 0.f)
                + 2.7557319224e-6f * a[off]
                + 2.7557319224e-7f * b[off]
                + 2.5052108385e-8f * d[off]
                + 2.0876756988e-9f * c[off];
        e[off] = v;
    }
    __syncthreads();
    mm64(f, c, e, ty, tx);
    __syncthreads();

#pragma unroll
    for (int l = 0; l < 16; l++) {
        int idx = tid + l * 256;
        int i = idx >> 6, j = idx & 63;
        int off = i * PA + j;
        float v = 4.1666666667e-2f * ((i == j) ? 1.f : 0.f)
                + 8.3333333333e-3f * a[off]
                + 1.3888888889e-3f * b[off]
                + 1.9841269841e-4f * d[off]
                + f[off];
        e[off] = v;
    }
    __syncthreads();
    mm64(f, c, e, ty, tx);
    __syncthreads();

#pragma unroll
    for (int l = 0; l < 16; l++) {
        int idx = tid + l * 256;
        int i = idx >> 6, j = idx & 63;
        int off = i * PA + j;
        float v = ((i == j) ? 1.f : 0.f)
                + a[off]
                + 0.5f * b[off]
                + 1.6666666667e-1f * d[off]
                + f[off];
        e[off] = v;
    }
    __syncthreads();
    mm64(f, e, e, ty, tx);
    __syncthreads();

#pragma unroll
    for (int l = 0; l < 16; l++) {
        int o = tid + l * 256;        // o = j*64 + i
        g_matsT[bt * 4096 + o] = f[(o & 63) * PA + (o >> 6)];
    }
}

// ---------------- traj phase: f32x2 packed FMA ----------------
// out[b, t, i] = sum_j mats[t][i][j] * x0[b][j]
// Block: one t, 128 batch rows. 256 threads; microtile 4b x 8i per thread.
// Warp layout: i_grp = tid&7 (4-way mat broadcast), b_grp = tid>>3 (8-way x broadcast).
extern "C" __global__ void __launch_bounds__(256)
traj_kernel(const float* __restrict__ inputs, float* __restrict__ out) {
    extern __shared__ float smraw[];
    float* mt = smraw;                 // mt[j*64 + i]   (16384 B)
    float* xt = smraw + 64 * 64;       // xt[j*PBX + b]  (33792 B)

    const int tid = threadIdx.x;
    const int ig = tid & 7;            // i0 = ig*8
    const int bg = tid >> 3;           // b_local = bg*4   (0..31 -> 128 rows)
    const int t  = blockIdx.y;
    const int b0 = blockIdx.x * 128;

    // Load mats[t] (transposed layout matches) straight into smem
    {
        const float4* msrc = (const float4*)(g_matsT + t * 4096);
        float4* mdst = (float4*)mt;
#pragma unroll
        for (int v = 0; v < 4; v++) mdst[v * 256 + tid] = msrc[v * 256 + tid];
    }

    // Load x0 tile transposed: 128 rows of inputs[:,0,:]
    {
        int bl = tid >> 1;             // 0..127
        int seg = tid & 1;             // j half
        const float* gp = inputs + (size_t)(b0 + bl) * TD + seg * 32;
#pragma unroll
        for (int q = 0; q < 8; q++) {
            float4 v = *(const float4*)(gp + q * 4);
            int j = seg * 32 + q * 4;
            xt[(j + 0) * PBX + bl] = v.x;
            xt[(j + 1) * PBX + bl] = v.y;
            xt[(j + 2) * PBX + bl] = v.z;
            xt[(j + 3) * PBX + bl] = v.w;
        }
    }
    __syncthreads();

    u64 acc[4][4];
#pragma unroll
    for (int r = 0; r < 4; r++)
#pragma unroll
        for (int c = 0; c < 4; c++) acc[r][c] = 0ull;

    const float* xrow = xt + bg * 4;
    const u64*  mrow = (const u64*)(mt + ig * 8);

#pragma unroll 8
    for (int j = 0; j < 64; j++) {
        // mat: 8 i-values as 4 packed f32x2 (naturally paired in smem)
        ulonglong2 ma = *(const ulonglong2*)(mrow + (size_t)j * 32);      // j*64 floats = j*32 u64
        ulonglong2 mb = *(const ulonglong2*)(mrow + (size_t)j * 32 + 2);
        u64 m[4] = {ma.x, ma.y, mb.x, mb.y};

        // x: 4 b-values, broadcast-duplicated into both halves
        float4 xv = *(const float4*)(xrow + (size_t)j * PBX);
        u64 bp[4] = {pack2(xv.x), pack2(xv.y), pack2(xv.z), pack2(xv.w)};

#pragma unroll
        for (int r = 0; r < 4; r++)
#pragma unroll
            for (int c = 0; c < 4; c++)
                acc[r][c] = ffma2(m[c], bp[r], acc[r][c]);
    }

    // Store: per b row, 8 contiguous floats (2x float4); warp covers 256B rows
#pragma unroll
    for (int r = 0; r < 4; r++) {
        float2 p0 = unpack2(acc[r][0]);
        float2 p1 = unpack2(acc[r][1]);
        float2 p2 = unpack2(acc[r][2]);
        float2 p3 = unpack2(acc[r][3]);
        float* op = out + (size_t)(b0 + bg * 4 + r) * TD + t * 64 + ig * 8;
        *(float4*)(op)     = make_float4(p0.x, p0.y, p1.x, p1.y);
        *(float4*)(op + 4) = make_float4(p2.x, p2.y, p3.x, p3.y);
    }
}

extern "C" void kernel_launch(void* const* d_in, const int* in_sizes, int n_in,
                              void* d_out, int out_size) {
    const float* inputs = (const float*)d_in[0];
    const float* time   = (const float*)d_in[1];
    const float* kern   = (const float*)d_in[2];
    float* out = (float*)d_out;

    static int configured = 0;
    const int smemA = 6 * 64 * PA * sizeof(float);             // 97.5 KB
    const int smemT = (64 * 64 + 64 * PBX) * sizeof(float);    // 50176 B
    if (!configured) {
        cudaFuncSetAttribute(expm_kernel, cudaFuncAttributeMaxDynamicSharedMemorySize, smemA);
        cudaFuncSetAttribute(traj_kernel, cudaFuncAttributeMaxDynamicSharedMemorySize, smemT);
        configured = 1;
    }

    expm_kernel<<<T_DIM, 256, smemA>>>(kern, time);
    traj_kernel<<<dim3(B_DIM / 128, T_DIM), 256, smemT>>>(inputs, out);
}

// round 4
// speedup vs baseline: 3.0179x; 3.0179x over previous
#include <cuda_runtime.h>
#include <cuda_bf16.h>
#include <cstdint>

// Problem shape
#define B_DIM 4096
#define T_DIM 256
#define TD 16384             // T*D stride per batch row
#define PA 68                // expm smem pad (float4-aligned rows)
#define T_PER_CTA 4

// Fragment-ordered operands in global memory.
// A (x0) fragments: idx = ((bblk*8 + w)*4 + ks)*32 + lane, one uint4 each (a0..a3)
__device__ uint4 g_xfH[32 * 8 * 4 * 32];
__device__ uint4 g_xfL[32 * 8 * 4 * 32];
// B (mats) fragments: idx = t*1024 + (ks*8 + f)*32 + lane, uint4 = (b0h, b1h, b0l, b1l)
__device__ uint4 g_mfrag[T_DIM * 1024];

// ---------------- helpers ----------------
__device__ __forceinline__ void split2(float x, float y, uint32_t& H, uint32_t& L) {
    __nv_bfloat16 hx = __float2bfloat16(x);
    __nv_bfloat16 hy = __float2bfloat16(y);
    float lx = x - __bfloat162float(hx);
    float ly = y - __bfloat162float(hy);
    __nv_bfloat16 lxb = __float2bfloat16(lx);
    __nv_bfloat16 lyb = __float2bfloat16(ly);
    H = ((uint32_t)__bfloat16_as_ushort(hy) << 16) | (uint32_t)__bfloat16_as_ushort(hx);
    L = ((uint32_t)__bfloat16_as_ushort(lyb) << 16) | (uint32_t)__bfloat16_as_ushort(lxb);
}

__device__ __forceinline__ void mma16816(float* c, const uint4& a, uint32_t b0, uint32_t b1) {
    asm volatile(
        "mma.sync.aligned.m16n8k16.row.col.f32.bf16.bf16.f32 "
        "{%0,%1,%2,%3}, {%4,%5,%6,%7}, {%8,%9}, {%0,%1,%2,%3};"
        : "+f"(c[0]), "+f"(c[1]), "+f"(c[2]), "+f"(c[3])
        : "r"(a.x), "r"(a.y), "r"(a.z), "r"(a.w), "r"(b0), "r"(b1));
}

// ---------------- expm phase (validated R1 math: Taylor-12 PS + 1 squaring) ----------------
__device__ __forceinline__ void mm64(float* __restrict__ C,
                                     const float* __restrict__ A,
                                     const float* __restrict__ B,
                                     int ty, int tx) {
    float acc[4][4];
#pragma unroll
    for (int r = 0; r < 4; r++)
#pragma unroll
        for (int c = 0; c < 4; c++) acc[r][c] = 0.f;

#pragma unroll 4
    for (int k = 0; k < 64; k++) {
        float4 bq = *(const float4*)&B[k * PA + tx * 4];
        float b[4] = {bq.x, bq.y, bq.z, bq.w};
        float a[4];
#pragma unroll
        for (int r = 0; r < 4; r++) a[r] = A[(ty * 4 + r) * PA + k];
#pragma unroll
        for (int r = 0; r < 4; r++)
#pragma unroll
            for (int c = 0; c < 4; c++) acc[r][c] = fmaf(a[r], b[c], acc[r][c]);
    }
#pragma unroll
    for (int r = 0; r < 4; r++)
#pragma unroll
        for (int c = 0; c < 4; c++) C[(ty * 4 + r) * PA + tx * 4 + c] = acc[r][c];
}

extern "C" __global__ void __launch_bounds__(256)
expm_kernel(const float* __restrict__ Kmat, const float* __restrict__ time) {
    extern __shared__ float sm[];
    float* a = sm;             // A = K*t/2
    float* b = a + 64 * PA;    // A^2
    float* c = b + 64 * PA;    // A^4
    float* d = c + 64 * PA;    // A^3
    float* e = d + 64 * PA;    // poly combos
    float* f = e + 64 * PA;    // products / result

    const int tid = threadIdx.x;
    const int ty = tid >> 4, tx = tid & 15;
    const int bt = blockIdx.x;
    const float t = time[bt] * 0.5f;   // scaling step s=1

#pragma unroll
    for (int l = 0; l < 16; l++) {
        int idx = tid + l * 256;
        a[(idx >> 6) * PA + (idx & 63)] = Kmat[idx] * t;
    }
    __syncthreads();

    mm64(b, a, a, ty, tx);            // A^2
    __syncthreads();
    mm64(c, b, b, ty, tx);            // A^4
    mm64(d, b, a, ty, tx);            // A^3
    __syncthreads();

#pragma unroll
    for (int l = 0; l < 16; l++) {
        int idx = tid + l * 256;
        int i = idx >> 6, j = idx & 63;
        int off = i * PA + j;
        e[off] = 2.4801587301e-5f * ((i == j) ? 1.f : 0.f)
               + 2.7557319224e-6f * a[off]
               + 2.7557319224e-7f * b[off]
               + 2.5052108385e-8f * d[off]
               + 2.0876756988e-9f * c[off];
    }
    __syncthreads();
    mm64(f, c, e, ty, tx);
    __syncthreads();

#pragma unroll
    for (int l = 0; l < 16; l++) {
        int idx = tid + l * 256;
        int i = idx >> 6, j = idx & 63;
        int off = i * PA + j;
        e[off] = 4.1666666667e-2f * ((i == j) ? 1.f : 0.f)
               + 8.3333333333e-3f * a[off]
               + 1.3888888889e-3f * b[off]
               + 1.9841269841e-4f * d[off]
               + f[off];
    }
    __syncthreads();
    mm64(f, c, e, ty, tx);
    __syncthreads();

#pragma unroll
    for (int l = 0; l < 16; l++) {
        int idx = tid + l * 256;
        int i = idx >> 6, j = idx & 63;
        int off = i * PA + j;
        e[off] = ((i == j) ? 1.f : 0.f)
               + a[off]
               + 0.5f * b[off]
               + 1.6666666667e-1f * d[off]
               + f[off];
    }
    __syncthreads();
    mm64(f, e, e, ty, tx);            // expm(K*t) = expm(A)^2, result in f[i][j]
    __syncthreads();

    // Pack B fragments: for (ks, fcol, lane): n = fcol*8 + lane/4, k = ks*16 + (lane%4)*2
    // b0 = M[n][k..k+1], b1 = M[n][k+8..k+9]; uint4 = (b0h, b1h, b0l, b1l)
#pragma unroll
    for (int l = 0; l < 4; l++) {
        int fi = tid + l * 256;            // 0..1023
        int lane = fi & 31;
        int fc = (fi >> 5) & 7;
        int ks = fi >> 8;
        int n = fc * 8 + (lane >> 2);
        int k = ks * 16 + (lane & 3) * 2;
        const float* R = f + n * PA;
        uint32_t b0h, b0l, b1h, b1l;
        split2(R[k], R[k + 1], b0h, b0l);
        split2(R[k + 8], R[k + 9], b1h, b1l);
        g_mfrag[bt * 1024 + fi] = make_uint4(b0h, b1h, b0l, b1l);
    }
}

// ---------------- x0 -> A fragments ----------------
extern "C" __global__ void __launch_bounds__(256)
xfrag_kernel(const float* __restrict__ inputs) {
    int idx = blockIdx.x * 256 + threadIdx.x;   // 0..32767
    int lane = idx & 31;
    int ks = (idx >> 5) & 3;
    int w = (idx >> 7) & 7;
    int bblk = idx >> 10;
    int m = bblk * 128 + w * 16 + (lane >> 2);
    int k = ks * 16 + (lane & 3) * 2;

    const float* r0 = inputs + (size_t)m * TD;
    const float* r1 = inputs + (size_t)(m + 8) * TD;
    float2 v00 = *(const float2*)(r0 + k);       // a0
    float2 v01 = *(const float2*)(r0 + k + 8);   // a2
    float2 v10 = *(const float2*)(r1 + k);       // a1
    float2 v11 = *(const float2*)(r1 + k + 8);   // a3

    uint4 H, L;
    split2(v00.x, v00.y, H.x, L.x);
    split2(v10.x, v10.y, H.y, L.y);
    split2(v01.x, v01.y, H.z, L.z);
    split2(v11.x, v11.y, H.w, L.w);
    g_xfH[idx] = H;
    g_xfL[idx] = L;
}

// ---------------- traj: pure HMMA kernel (no smem) ----------------
// CTA = (bblk: 128 b-rows, tblk: 4 t's). Warp w owns m-rows w*16..+15, all n=64.
// D[m][n] = sum_k x[b0+m][k] * M[t][n][k] via 3-term bf16 split, fp32 accum.
extern "C" __global__ void __launch_bounds__(256)
traj_kernel(float* __restrict__ out) {
    const int tid = threadIdx.x;
    const int wid = tid >> 5, lane = tid & 31;
    const int bblk = blockIdx.x;
    const int tblk = blockIdx.y;

    // Loop-invariant A fragments (hi+lo, 4 k-steps)
    uint4 aH[4], aL[4];
    {
        int ab = ((bblk * 8 + wid) * 4) * 32 + lane;
#pragma unroll
        for (int ks = 0; ks < 4; ks++) {
            aH[ks] = g_xfH[ab + ks * 32];
            aL[ks] = g_xfL[ab + ks * 32];
        }
    }

    const int m0 = bblk * 128 + wid * 16 + (lane >> 2);
    const int c0 = (lane & 3) * 2;

#pragma unroll 1
    for (int tt = 0; tt < T_PER_CTA; tt++) {
        const int t = tblk * T_PER_CTA + tt;
        float acc[8][4];
#pragma unroll
        for (int f = 0; f < 8; f++)
#pragma unroll
            for (int q = 0; q < 4; q++) acc[f][q] = 0.f;

        const uint4* bp = g_mfrag + t * 1024 + lane;
#pragma unroll
        for (int ks = 0; ks < 4; ks++) {
#pragma unroll
            for (int f = 0; f < 8; f++) {
                uint4 bfr = bp[(ks * 8 + f) * 32];
                mma16816(acc[f], aH[ks], bfr.x, bfr.y);   // hi*hi
                mma16816(acc[f], aL[ks], bfr.x, bfr.y);   // lo*hi
                mma16816(acc[f], aH[ks], bfr.z, bfr.w);   // hi*lo
            }
        }

        float* ob  = out + (size_t)m0 * TD + t * 64 + c0;
        float* ob8 = ob + (size_t)8 * TD;
#pragma unroll
        for (int f = 0; f < 8; f++) {
            *(float2*)(ob  + f * 8) = make_float2(acc[f][0], acc[f][1]);
            *(float2*)(ob8 + f * 8) = make_float2(acc[f][2], acc[f][3]);
        }
    }
}

// ---------------- launch ----------------
extern "C" void kernel_launch(void* const* d_in, const int* in_sizes, int n_in,
                              void* d_out, int out_size) {
    const float* inputs = (const float*)d_in[0];
    const float* time   = (const float*)d_in[1];
    const float* kern   = (const float*)d_in[2];
    float* out = (float*)d_out;

    const int smemA = 6 * 64 * PA * sizeof(float);   // 104448 B
    cudaFuncSetAttribute(expm_kernel, cudaFuncAttributeMaxDynamicSharedMemorySize, smemA);

    xfrag_kernel<<<128, 256>>>(inputs);
    expm_kernel<<<T_DIM, 256, smemA>>>(kern, time);
    traj_kernel<<<dim3(32, T_DIM / T_PER_CTA), 256>>>(out);
}